// round 15
// baseline (speedup 1.0000x reference)
#include <cuda_runtime.h>
#include <cuda_bf16.h>

#define N_CORES   64
#define N_QUBITS  1024
#define QEMB      256
#define N_EDGES   448
#define BATCH     512

// Scratch: ping-pong activation buffers, max width 512.
__device__ float g_buf0[BATCH * N_CORES * 512];
__device__ float g_buf1[BATCH * N_CORES * 512];
__device__ float g_A[N_CORES * N_CORES];

// ---------------- packed f32x2 helpers (Blackwell FFMA2 path) ----------------
__device__ __forceinline__ unsigned long long ffma2(unsigned long long a,
                                                    unsigned long long b,
                                                    unsigned long long c)
{
    unsigned long long d;
    asm("fma.rn.f32x2 %0, %1, %2, %3;" : "=l"(d) : "l"(a), "l"(b), "l"(c));
    return d;
}
__device__ __forceinline__ unsigned long long pack2(float x, float y)
{
    unsigned long long r;
    asm("mov.b64 %0, {%1, %2};" : "=l"(r) : "f"(x), "f"(y));
    return r;
}
__device__ __forceinline__ float2 unpack2(unsigned long long v)
{
    float2 r;
    asm("mov.b64 {%0, %1}, %2;" : "=f"(r.x), "=f"(r.y) : "l"(v));
    return r;
}

// ---------------------------------------------------------------------------
// Kernel 1: dense normalized adjacency A[out*64 + src] (with self loops)
// ---------------------------------------------------------------------------
__global__ void prep_A_kernel(const int* __restrict__ eidx,
                              const float* __restrict__ ew,
                              float* __restrict__ A_out)
{
    __shared__ float sdeg[N_CORES];
    __shared__ float sdinv[N_CORES];
    __shared__ float sA[N_CORES * N_CORES];
    const int t = threadIdx.x;  // 256 threads

    if (t < N_CORES) sdeg[t] = 1.0f;
    for (int i = t; i < N_CORES * N_CORES; i += 256) sA[i] = 0.0f;
    __syncthreads();

    for (int e = t; e < N_EDGES; e += 256) {
        int c = eidx[N_EDGES + e];
        atomicAdd(&sdeg[c], ew[e]);
    }
    __syncthreads();

    if (t < N_CORES) sdinv[t] = 1.0f / sqrtf(sdeg[t]);
    __syncthreads();

    for (int e = t; e < N_EDGES; e += 256) {
        int r = eidx[e];
        int c = eidx[N_EDGES + e];
        atomicAdd(&sA[c * N_CORES + r], sdinv[r] * ew[e] * sdinv[c]);
    }
    if (t < N_CORES) atomicAdd(&sA[t * N_CORES + t], sdinv[t] * sdinv[t]);
    __syncthreads();

    for (int i = t; i < N_CORES * N_CORES; i += 256) A_out[i] = sA[i];
}

// ---------------------------------------------------------------------------
// Kernel 2: pooling. grid = (BATCH, 2); block = 128 threads.
// ---------------------------------------------------------------------------
__global__ void pool_kernel(const int* __restrict__ core_allocs,
                            const float* __restrict__ qubit_embs,
                            const float* __restrict__ dummy_emb,
                            float* __restrict__ x0)
{
    __shared__ int   s_alloc[N_QUBITS];
    __shared__ float smax[N_CORES * 128];

    const int b    = blockIdx.x;
    const int half = blockIdx.y;
    const int t    = threadIdx.x;
    const int d    = half * 128 + t;

    const int* arow = core_allocs + b * N_QUBITS;
    for (int q = t; q < N_QUBITS; q += 128) s_alloc[q] = arow[q];

    const float dv = dummy_emb[d];
    #pragma unroll
    for (int c = 0; c < N_CORES; c++) smax[c * 128 + t] = dv;
    __syncthreads();

    #pragma unroll 4
    for (int q = 0; q < N_QUBITS; q++) {
        int c = s_alloc[q];
        float v = __ldg(&qubit_embs[q * QEMB + d]);
        float* p = &smax[c * 128 + t];
        *p = fmaxf(*p, v);
    }
    __syncthreads();

    float* xb = x0 + (size_t)b * N_CORES * QEMB;
    #pragma unroll
    for (int c = 0; c < N_CORES; c++) {
        xb[c * QEMB + d] = smax[c * 128 + t];
    }
}

// ---------------------------------------------------------------------------
// Kernel 3: fused GCN layer, 128x128 output tile (2 batches x 128 cols).
//   Phase 1: H = X @ W tile, 8x8 micro-tiles via packed FFMA2 (f32x2).
//   Phase 2: out = relu(blockdiag(A,A) @ H + b) via 4 strips of 32 cols.
// grid = (DOUT/128, BATCH/2), block = 256.
// ---------------------------------------------------------------------------
template <int DIN, int DOUT>
__global__ __launch_bounds__(256, 2)
void gcn_layer_kernel(const float* __restrict__ x,
                      const float* __restrict__ W,
                      const float* __restrict__ bias,
                      const float* __restrict__ A,
                      float* __restrict__ out)
{
    // union buffer:
    //   phase1: sXT[32][132] (4224) + sW[32][128] (4096) = 8320
    //   phase2: sHs[128][36] (4608) + sAT[64][68]  (4352) = 8960
    __shared__ float sbuf[8960];
    float* sXT = sbuf;            // k-major transposed X chunk
    float* sW  = sbuf + 4224;
    float* sHs = sbuf;            // phase-2 H strip
    float* sAT = sbuf + 4608;     // A transposed, k-major

    const int tid = threadIdx.x;
    const int tx  = tid & 15;
    const int ty  = tid >> 4;
    const int n0  = blockIdx.x * 128;
    const float* X = x + (size_t)blockIdx.y * 128 * DIN;  // 2 consecutive batches

    // packed accumulators: acc2[i][jp] covers cols pairs
    //   jp0: (tx*4+0, +1)   jp1: (tx*4+2, +3)
    //   jp2: (64+tx*4+0,+1) jp3: (64+tx*4+2,+3)
    unsigned long long acc2[8][4];
    #pragma unroll
    for (int i = 0; i < 8; i++)
        #pragma unroll
        for (int j = 0; j < 4; j++) acc2[i][j] = 0ull;

    // ---- Phase 1: K-chunks of 32 ----
    for (int k0 = 0; k0 < DIN; k0 += 32) {
        // X chunk [128 rows x 32 k] -> transposed sXT[k][row] (stride 132)
        #pragma unroll
        for (int it = 0; it < 4; it++) {
            int idx = tid + it * 256;          // 0..1023 float4 slots
            int r   = idx >> 3;                // 0..127
            int kq  = (idx & 7) * 4;           // 0..28
            float4 v = *(const float4*)(X + (size_t)r * DIN + k0 + kq);
            sXT[(kq + 0) * 132 + r] = v.x;
            sXT[(kq + 1) * 132 + r] = v.y;
            sXT[(kq + 2) * 132 + r] = v.z;
            sXT[(kq + 3) * 132 + r] = v.w;
        }
        // W chunk [32 k x 128 cols] -> sW (stride 128)
        #pragma unroll
        for (int it = 0; it < 4; it++) {
            int idx = tid + it * 256;
            int kk  = idx >> 5;                // 0..31
            int n4  = (idx & 31) * 4;          // 0..124
            *(float4*)&sW[kk * 128 + n4] =
                *(const float4*)(W + (size_t)(k0 + kk) * DOUT + n0 + n4);
        }
        __syncthreads();

        #pragma unroll 8
        for (int k = 0; k < 32; k++) {
            float4 a0 = *(float4*)&sXT[k * 132 + ty * 4];
            float4 a1 = *(float4*)&sXT[k * 132 + 64 + ty * 4];
            ulonglong2 w0 = *(ulonglong2*)&sW[k * 128 + tx * 4];
            ulonglong2 w1 = *(ulonglong2*)&sW[k * 128 + 64 + tx * 4];
            float av[8] = {a0.x, a0.y, a0.z, a0.w, a1.x, a1.y, a1.z, a1.w};
            #pragma unroll
            for (int i = 0; i < 8; i++) {
                unsigned long long ad = pack2(av[i], av[i]);
                acc2[i][0] = ffma2(w0.x, ad, acc2[i][0]);
                acc2[i][1] = ffma2(w0.y, ad, acc2[i][1]);
                acc2[i][2] = ffma2(w1.x, ad, acc2[i][2]);
                acc2[i][3] = ffma2(w1.y, ad, acc2[i][3]);
            }
        }
        __syncthreads();
    }

    // ---- load A (transposed, k-major) into union buffer ----
    for (int i = tid; i < N_CORES * N_CORES; i += 256) {
        int c = i >> 6, k = i & 63;
        sAT[k * 68 + c] = A[i];   // A[c*64 + k]
    }

    // ---- Phase 2: 4 strips of 32 columns ----
    #pragma unroll
    for (int s = 0; s < 4; s++) {
        const int g = s >> 1;            // acc column half
        if ((tx >> 3) == (s & 1)) {
            int sc = (tx & 7) * 4;       // col within strip
            #pragma unroll
            for (int i = 0; i < 8; i++) {
                int row = (i < 4) ? (ty * 4 + i) : (64 + ty * 4 + (i - 4));
                ulonglong2 v;
                v.x = acc2[i][g * 2 + 0];
                v.y = acc2[i][g * 2 + 1];
                *(ulonglong2*)&sHs[row * 36 + sc] = v;
            }
        }
        __syncthreads();

        unsigned long long o2[8];
        #pragma unroll
        for (int i = 0; i < 8; i++) o2[i] = 0ull;

        #pragma unroll 8
        for (int k = 0; k < 64; k++) {
            float4 av = *(float4*)&sAT[k * 68 + ty * 4];
            unsigned long long h0 = *(unsigned long long*)&sHs[k * 36 + tx * 2];
            unsigned long long h1 = *(unsigned long long*)&sHs[(64 + k) * 36 + tx * 2];
            unsigned long long dx = pack2(av.x, av.x);
            unsigned long long dy = pack2(av.y, av.y);
            unsigned long long dz = pack2(av.z, av.z);
            unsigned long long dw = pack2(av.w, av.w);
            o2[0] = ffma2(h0, dx, o2[0]);
            o2[1] = ffma2(h0, dy, o2[1]);
            o2[2] = ffma2(h0, dz, o2[2]);
            o2[3] = ffma2(h0, dw, o2[3]);
            o2[4] = ffma2(h1, dx, o2[4]);
            o2[5] = ffma2(h1, dy, o2[5]);
            o2[6] = ffma2(h1, dz, o2[6]);
            o2[7] = ffma2(h1, dw, o2[7]);
        }

        float2 bv = *(const float2*)(bias + n0 + 32 * s + tx * 2);
        #pragma unroll
        for (int i = 0; i < 8; i++) {
            int batch = blockIdx.y * 2 + (i < 4 ? 0 : 1);
            int core  = ty * 4 + (i & 3);
            float2 ov = unpack2(o2[i]);
            float2 r;
            r.x = fmaxf(ov.x + bv.x, 0.0f);
            r.y = fmaxf(ov.y + bv.y, 0.0f);
            *(float2*)(out + ((size_t)batch * 64 + core) * DOUT + n0 + 32 * s + tx * 2) = r;
        }
        if (s < 3) __syncthreads();
    }
}

// ---------------------------------------------------------------------------
// Launch
// ---------------------------------------------------------------------------
extern "C" void kernel_launch(void* const* d_in, const int* in_sizes, int n_in,
                              void* d_out, int out_size)
{
    const int*   core_allocs = (const int*)d_in[0];    // [512,1024]
    const float* qubit_embs  = (const float*)d_in[1];  // [1024,256]
    const float* dummy_emb   = (const float*)d_in[2];  // [256]
    const int*   edge_index  = (const int*)d_in[3];    // [2,448]
    const float* edge_weight = (const float*)d_in[4];  // [448]
    const float* W1 = (const float*)d_in[5];           // [256,512]
    const float* b1 = (const float*)d_in[6];           // [512]
    const float* W2 = (const float*)d_in[7];           // [512,512]
    const float* b2 = (const float*)d_in[8];           // [512]
    const float* W3 = (const float*)d_in[9];           // [512,256]
    const float* b3 = (const float*)d_in[10];          // [256]
    float* out = (float*)d_out;                        // [512,64,256]

    float *p0 = nullptr, *p1 = nullptr, *pA = nullptr;
    cudaGetSymbolAddress((void**)&p0, g_buf0);
    cudaGetSymbolAddress((void**)&p1, g_buf1);
    cudaGetSymbolAddress((void**)&pA, g_A);

    // 1) dense normalized adjacency
    prep_A_kernel<<<1, 256>>>(edge_index, edge_weight, pA);

    // 2) pooling -> g_buf0 [512,64,256]
    pool_kernel<<<dim3(BATCH, 2), 128>>>(core_allocs, qubit_embs, dummy_emb, p0);

    // 3) three fused GCN layers (128-row tiles = 2 batches per block)
    gcn_layer_kernel<256, 512><<<dim3(512 / 128, BATCH / 2), 256>>>(p0, W1, b1, pA, p1);
    gcn_layer_kernel<512, 512><<<dim3(512 / 128, BATCH / 2), 256>>>(p1, W2, b2, pA, p0);
    gcn_layer_kernel<512, 256><<<dim3(256 / 128, BATCH / 2), 256>>>(p0, W3, b3, pA, out);
}